// round 15
// baseline (speedup 1.0000x reference)
#include <cuda_runtime.h>
#include <cuda_bf16.h>
#include <math.h>
#include <stdint.h>

#define LSEQ 4096
#define DMODEL 768
#define BATCH 4
#define NFFT 8192
#define HALF_NFFT 4096
#define HSTRIDE 4104   // half-spectrum storage stride (4097 used, padded)

// ---------------- scratch (device globals; no allocation allowed) ----------------
__device__ float  g_h[(size_t)LSEQ * DMODEL];                    // filters h[t][d]
__device__ float2 g_Hf[(size_t)DMODEL * HSTRIDE];                // natural-order half spectra
__device__ float  g_up[(size_t)BATCH * LSEQ * 2304];             // u @ proj_W + b
__device__ float  g_qT[(size_t)BATCH * DMODEL * LSEQ];           // q = v*x0, channel-major
__device__ float  g_x1T[(size_t)BATCH * DMODEL * LSEQ];          // x1, channel-major
__device__ float  g_wT[(size_t)BATCH * DMODEL * LSEQ];           // (vnew*x1), channel-major
__device__ float2 g_tw[HALF_NFFT];                               // twiddles exp(-2*pi*i*k/NFFT)

__device__ __forceinline__ int br13(int k) { return (int)(__brev((unsigned)k) >> 19); }

// ---------------- packed f32x2 helpers (Blackwell base ISA) ----------------
__device__ __forceinline__ void ffma2(unsigned long long& d, unsigned long long a,
                                      unsigned long long b) {
    asm("fma.rn.f32x2 %0, %1, %2, %0;" : "+l"(d) : "l"(a), "l"(b));
}
__device__ __forceinline__ unsigned long long packab(float lo, float hi) {
    unsigned long long r;
    asm("mov.b64 %0, {%1, %2};" : "=l"(r) : "f"(lo), "f"(hi));
    return r;
}
__device__ __forceinline__ float2 unpack2(unsigned long long v) {
    float2 r;
    asm("mov.b64 {%0, %1}, %2;" : "=f"(r.x), "=f"(r.y) : "l"(v));
    return r;
}

// ---------------- twiddle init ----------------
__global__ void k_twiddle() {
    int k = blockIdx.x * blockDim.x + threadIdx.x;
    if (k < HALF_NFFT) {
        double s, c;
        sincospi(-2.0 * (double)k / (double)NFFT, &s, &c);
        g_tw[k] = make_float2((float)c, (float)s);
    }
}

// ---------------- filter MLP: h[t][d] ----------------
__global__ void k_filter(const float* __restrict__ z, const float* __restrict__ finW,
                         const float* __restrict__ finb, const float* __restrict__ freq,
                         const float* __restrict__ midW, const float* __restrict__ midb,
                         const float* __restrict__ foutW) {
    __shared__ float s_x[32][66];
    __shared__ float s_y[32][66];
    __shared__ float s_w[65][65];
    __shared__ float s_bias[64];
    __shared__ float s_freq[64];
    int t0 = blockIdx.x * 32;
    int tid = threadIdx.x;

    for (int i = tid; i < 32 * 65; i += 256) {
        int r = i / 65, c = i % 65;
        s_x[r][c] = z[(size_t)(t0 + r) * 65 + c];
    }
    for (int i = tid; i < 65 * 64; i += 256) s_w[i / 64][i % 64] = finW[i];
    if (tid < 64) { s_bias[tid] = finb[tid]; s_freq[tid] = freq[tid]; }
    __syncthreads();

    for (int i = tid; i < 2048; i += 256) {
        int r = i >> 6, j = i & 63;
        float acc = s_bias[j];
        #pragma unroll
        for (int kk = 0; kk < 65; kk++) acc += s_x[r][kk] * s_w[kk][j];
        s_y[r][j] = sinf(s_freq[j] * acc);
    }
    __syncthreads();

    for (int layer = 0; layer < 2; layer++) {
        for (int i = tid; i < 4096; i += 256) s_w[i >> 6][i & 63] = midW[layer * 4096 + i];
        if (tid < 64) s_bias[tid] = midb[layer * 64 + tid];
        __syncthreads();
        float (*src)[66] = (layer == 0) ? s_y : s_x;
        float (*dst)[66] = (layer == 0) ? s_x : s_y;
        for (int i = tid; i < 2048; i += 256) {
            int r = i >> 6, j = i & 63;
            float acc = s_bias[j];
            #pragma unroll
            for (int kk = 0; kk < 64; kk++) acc += src[r][kk] * s_w[kk][j];
            dst[r][j] = sinf(s_freq[j] * acc);
        }
        __syncthreads();
    }
    const float LOGT = -4.605170185988091f;            // ln(0.01)
    const float mind = LOGT / 1.5f;
    const float maxd = LOGT / 0.3f;
    for (int c = 0; c < 12; c++) {
        for (int i = tid; i < 4096; i += 256)
            s_w[i >> 6][i & 63] = foutW[(size_t)(i >> 6) * 768 + c * 64 + (i & 63)];
        __syncthreads();
        for (int i = tid; i < 2048; i += 256) {
            int r = i >> 6, dd = i & 63;
            float acc = 0.f;
            #pragma unroll
            for (int j = 0; j < 64; j++) acc += s_y[r][j] * s_w[j][dd];
            int t = t0 + r;
            int d = c * 64 + dd;
            float delta = fabsf(mind + (maxd - mind) * (float)d / 767.0f);
            float tt = (float)t / 4095.0f;
            g_h[(size_t)t * 768 + d] = acc * expf(-tt * delta);
        }
        __syncthreads();
    }
}

// ---------------- FFT primitives (radix-2; twiddles read from L1-cached global) ----------------
__device__ __forceinline__ void fft_dif(float2* x, const float2* __restrict__ tw, int tid) {
    #pragma unroll 1
    for (int s = 0; s < 13; s++) {
        int m = 4096 >> s;
        #pragma unroll
        for (int k = 0; k < 8; k++) {
            int bidx = tid + k * 512;
            int j = bidx & (m - 1);
            int g = bidx >> (12 - s);
            int i1 = (g << (13 - s)) + j;
            int i2 = i1 + m;
            float2 a = x[i1], c = x[i2];
            x[i1] = make_float2(a.x + c.x, a.y + c.y);
            float2 w = __ldg(&tw[j << s]);
            float dr = a.x - c.x, di = a.y - c.y;
            x[i2] = make_float2(dr * w.x - di * w.y, dr * w.y + di * w.x);
        }
        __syncthreads();
    }
}

__device__ __forceinline__ void fft_dit_inv(float2* x, const float2* __restrict__ tw, int tid) {
    #pragma unroll 1
    for (int s = 0; s < 13; s++) {
        int m = 1 << s;
        #pragma unroll
        for (int k = 0; k < 8; k++) {
            int bidx = tid + k * 512;
            int j = bidx & (m - 1);
            int g = bidx >> s;
            int i1 = (g << (s + 1)) + j;
            int i2 = i1 + m;
            float2 a = x[i1], b = x[i2];
            float2 w = __ldg(&tw[j << (12 - s)]);
            float cr = b.x * w.x + b.y * w.y;   // b * conj(w)
            float ci = b.y * w.x - b.x * w.y;
            x[i1] = make_float2(a.x + cr, a.y + ci);
            x[i2] = make_float2(a.x - cr, a.y - ci);
        }
        __syncthreads();
    }
}

// ---------------- filter FFT: one block per PAIR of channels ----------------
__global__ void k_fft_filter() {
    extern __shared__ unsigned char s_raw[];
    float2* x = (float2*)s_raw;
    int d0 = blockIdx.x * 2;
    int d1 = d0 + 1;
    int tid = threadIdx.x; // 512
    for (int i = tid; i < NFFT; i += 512) {
        float re = (i < LSEQ) ? g_h[(size_t)i * 768 + d0] : 0.f;
        float im = (i < LSEQ) ? g_h[(size_t)i * 768 + d1] : 0.f;
        x[i] = make_float2(re, im);
    }
    __syncthreads();
    fft_dif(x, g_tw, tid);
    const float sc = 0.5f / (float)NFFT;
    for (int k = tid; k <= HALF_NFFT; k += 512) {
        float2 Zk = x[br13(k)];
        float2 Zm = x[br13((NFFT - k) & (NFFT - 1))];
        float2 H0 = make_float2(sc * (Zk.x + Zm.x), sc * (Zk.y - Zm.y));
        float2 H1 = make_float2(sc * (Zk.y + Zm.y), sc * (Zm.x - Zk.x));
        g_Hf[(size_t)d0 * HSTRIDE + k] = H0;
        g_Hf[(size_t)d1 * HSTRIDE + k] = H1;
    }
}

// ---------------- GEMM helpers ----------------
// A smem: u64 As2[16][128], entry [kk][m] = (a,a) duplicated pair (LDS.64 broadcast).
// B smem: u64 Bs2[16][64], entry [kk][jp*16+tx] = cols (tx*8+2jp, tx*8+2jp+1).
__device__ __forceinline__ void stage_B(unsigned long long (*Bs2)[64],
                                        const float* __restrict__ B, int N,
                                        int k0, int bn, int tid) {
    #pragma unroll
    for (int li = 0; li < 2; li++) {
        int id = tid + li * 256;
        int brow = id >> 5, bc = (id & 31) * 4;
        float4 v = *(const float4*)&B[(size_t)(k0 + brow) * N + bn + bc];
        int txp = bc >> 3;
        int jpA = (bc & 7) >> 1;                 // 0 or 2
        Bs2[brow][jpA * 16 + txp]       = packab(v.x, v.y);
        Bs2[brow][(jpA + 1) * 16 + txp] = packab(v.z, v.w);
    }
}

__device__ __forceinline__ void gemm_step(const unsigned long long (*As2)[128],
                                          const unsigned long long (*Bs2)[64],
                                          int kk, int tx, int ty,
                                          unsigned long long (&acc2)[8][4]) {
    unsigned long long a2[8];
    #pragma unroll
    for (int i = 0; i < 8; i++)
        a2[i] = As2[kk][ty * 8 + i];
    unsigned long long b2[4];
    #pragma unroll
    for (int jp = 0; jp < 4; jp++)
        b2[jp] = Bs2[kk][jp * 16 + tx];
    #pragma unroll
    for (int i = 0; i < 8; i++)
        #pragma unroll
        for (int jp = 0; jp < 4; jp++)
            ffma2(acc2[i][jp], a2[i], b2[jp]);
}

// ---------------- proj GEMM: up = u @ proj_W + proj_b ----------------
__global__ void __launch_bounds__(256, 2) k_sgemm_proj(
    const float* __restrict__ A, const float* __restrict__ B,
    const float* __restrict__ bias) {
    const int K = 768, N = 2304;
    __shared__ unsigned long long As2[16][128];
    __shared__ unsigned long long Bs2[16][64];
    int tid = threadIdx.x;
    int bm = blockIdx.y * 128, bn = blockIdx.x * 128;
    int tx = tid & 15, ty = tid >> 4;
    unsigned long long acc2[8][4];
    #pragma unroll
    for (int i = 0; i < 8; i++)
        #pragma unroll
        for (int j = 0; j < 4; j++) acc2[i][j] = 0ull;

    for (int k0 = 0; k0 < K; k0 += 16) {
        #pragma unroll
        for (int li = 0; li < 2; li++) {
            int id = tid + li * 256;
            int ar = id >> 2, ac = (id & 3) * 4;
            float4 v = *(const float4*)&A[(size_t)(bm + ar) * K + k0 + ac];
            As2[ac + 0][ar] = packab(v.x, v.x);
            As2[ac + 1][ar] = packab(v.y, v.y);
            As2[ac + 2][ar] = packab(v.z, v.z);
            As2[ac + 3][ar] = packab(v.w, v.w);
        }
        stage_B(Bs2, B, N, k0, bn, tid);
        __syncthreads();
        #pragma unroll
        for (int kk = 0; kk < 16; kk++)
            gemm_step(As2, Bs2, kk, tx, ty, acc2);
        __syncthreads();
    }
    #pragma unroll
    for (int i = 0; i < 8; i++) {
        size_t row = (size_t)(bm + ty * 8 + i) * N + bn + tx * 8;
        #pragma unroll
        for (int jp = 0; jp < 4; jp++) {
            float2 v = unpack2(acc2[i][jp]);
            g_up[row + jp * 2 + 0] = v.x + bias[bn + tx * 8 + jp * 2 + 0];
            g_up[row + jp * 2 + 1] = v.y + bias[bn + tx * 8 + jp * 2 + 1];
        }
    }
}

// ---------------- short conv + split + transpose ----------------
__global__ void k_shortconv(const float* __restrict__ cw, const float* __restrict__ cb) {
    __shared__ float sq[32][33];
    __shared__ float sx1[32][33];
    int b = blockIdx.z;
    int t0 = blockIdx.x * 32, d0 = blockIdx.y * 32;
    int tx = threadIdx.x, ty = threadIdx.y;
    int t = t0 + ty;
    const float* up = g_up + (size_t)b * LSEQ * 2304;
    float vals[3];
    #pragma unroll
    for (int p = 0; p < 3; p++) {
        int c = d0 + tx + p * 768;
        float w0 = cw[c], w1 = cw[2304 + c], w2 = cw[4608 + c];
        float u2 = up[(size_t)t * 2304 + c];
        float u1 = (t >= 1) ? up[(size_t)(t - 1) * 2304 + c] : 0.f;
        float u0 = (t >= 2) ? up[(size_t)(t - 2) * 2304 + c] : 0.f;
        vals[p] = w0 * u0 + w1 * u1 + w2 * u2 + cb[c];
    }
    sq[ty][tx] = vals[2] * vals[0];   // q = v * x0
    sx1[ty][tx] = vals[1];
    __syncthreads();
    size_t o = ((size_t)b * DMODEL + d0 + ty) * LSEQ + t0 + tx;
    g_qT[o]  = sq[tx][ty];
    g_x1T[o] = sx1[tx][ty];
}

// ---------------- FFT conv: one block per (channel, batch-pair) ----------------
__global__ void k_fftconv(const float* __restrict__ fb) {
    extern __shared__ unsigned char s_raw[];
    float2* x = (float2*)s_raw;
    int d = blockIdx.x, bp = blockIdx.y;
    int b0 = bp * 2, b1 = b0 + 1;
    int tid = threadIdx.x; // 512
    size_t base0 = ((size_t)b0 * DMODEL + d) * LSEQ;
    size_t base1 = ((size_t)b1 * DMODEL + d) * LSEQ;
    const float* q0 = g_qT + base0;
    const float* q1 = g_qT + base1;

    float qr0[8], qr1[8];
    #pragma unroll
    for (int k = 0; k < 8; k++) {
        int i = tid + k * 512;
        qr0[k] = q0[i];
        qr1[k] = q1[i];
        x[i] = make_float2(qr0[k], qr1[k]);
    }
    #pragma unroll
    for (int k = 0; k < 8; k++) x[LSEQ + tid + k * 512] = make_float2(0.f, 0.f);
    __syncthreads();

    fft_dif(x, g_tw, tid);

    const float2* H = g_Hf + (size_t)d * HSTRIDE;
    for (int idx = tid; idx < HALF_NFFT; idx += 512) {
        if (idx == 0) {
            #pragma unroll
            for (int e = 0; e < 2; e++) {
                int pos = e;                       // br(0)=0, br(4096)=1
                float2 Z = x[pos];
                float2 h = H[e == 0 ? 0 : HALF_NFFT];
                float2 Y0 = make_float2(Z.x * h.x, Z.x * h.y);
                float2 Y1 = make_float2(Z.y * h.x, Z.y * h.y);
                x[pos] = make_float2(Y0.x - Y1.y, Y0.y + Y1.x);
            }
        } else {
            int k = idx;
            int p1 = br13(k);
            int p2 = br13(NFFT - k);
            float2 Zk = x[p1], Zm = x[p2];
            float2 Q0 = make_float2(0.5f * (Zk.x + Zm.x), 0.5f * (Zk.y - Zm.y));
            float2 Q1 = make_float2(0.5f * (Zk.y + Zm.y), 0.5f * (Zm.x - Zk.x));
            float2 h = H[k];
            float2 Y0 = make_float2(Q0.x * h.x - Q0.y * h.y, Q0.x * h.y + Q0.y * h.x);
            float2 Y1 = make_float2(Q1.x * h.x - Q1.y * h.y, Q1.x * h.y + Q1.y * h.x);
            x[p1] = make_float2(Y0.x - Y1.y, Y0.y + Y1.x);       // W(k)
            x[p2] = make_float2(Y0.x + Y1.y, Y1.x - Y0.y);       // W(N-k)
        }
    }
    __syncthreads();

    fft_dit_inv(x, g_tw, tid);

    float bias = fb[d];
    const float* x10 = g_x1T + base0;
    const float* x11 = g_x1T + base1;
    float* w0 = g_wT + base0;
    float* w1 = g_wT + base1;
    #pragma unroll
    for (int k = 0; k < 8; k++) {
        int i = tid + k * 512;
        float2 v = x[i];
        w0[i] = (v.x + qr0[k] * bias) * x10[i];
        w1[i] = (v.y + qr1[k] * bias) * x11[i];
    }
}

// ---------------- out GEMM: y = w @ out_W + out_b ----------------
__global__ void __launch_bounds__(256, 2) k_sgemm_out(
    const float* __restrict__ B, const float* __restrict__ bias,
    float* __restrict__ C) {
    const int K = 768, N = 768;
    __shared__ unsigned long long As2[16][128];
    __shared__ unsigned long long Bs2[16][64];
    int tid = threadIdx.x;
    int bm = blockIdx.y * 128, bn = blockIdx.x * 128;
    int b = bm >> 12;
    int t0 = bm & 4095;
    const float* Ab = g_wT + (size_t)b * DMODEL * LSEQ + t0; // A[i,k] = Ab[k*4096 + i]
    int tx = tid & 15, ty = tid >> 4;
    unsigned long long acc2[8][4];
    #pragma unroll
    for (int i = 0; i < 8; i++)
        #pragma unroll
        for (int j = 0; j < 4; j++) acc2[i][j] = 0ull;

    for (int k0 = 0; k0 < K; k0 += 16) {
        #pragma unroll
        for (int li = 0; li < 2; li++) {
            int id = tid + li * 256;
            int kc = id >> 5, i4 = (id & 31) * 4;
            float4 v = *(const float4*)&Ab[(size_t)(k0 + kc) * LSEQ + i4];
            As2[kc][i4 + 0] = packab(v.x, v.x);
            As2[kc][i4 + 1] = packab(v.y, v.y);
            As2[kc][i4 + 2] = packab(v.z, v.z);
            As2[kc][i4 + 3] = packab(v.w, v.w);
        }
        stage_B(Bs2, B, N, k0, bn, tid);
        __syncthreads();
        #pragma unroll
        for (int kk = 0; kk < 16; kk++)
            gemm_step(As2, Bs2, kk, tx, ty, acc2);
        __syncthreads();
    }
    #pragma unroll
    for (int i = 0; i < 8; i++) {
        size_t row = (size_t)(bm + ty * 8 + i) * N + bn + tx * 8;
        #pragma unroll
        for (int jp = 0; jp < 4; jp++) {
            float2 v = unpack2(acc2[i][jp]);
            C[row + jp * 2 + 0] = v.x + bias[bn + tx * 8 + jp * 2 + 0];
            C[row + jp * 2 + 1] = v.y + bias[bn + tx * 8 + jp * 2 + 1];
        }
    }
}

// ---------------- launch ----------------
extern "C" void kernel_launch(void* const* d_in, const int* in_sizes, int n_in,
                              void* d_out, int out_size) {
    (void)in_sizes; (void)n_in; (void)out_size;
    const float* u     = (const float*)d_in[0];
    const float* z     = (const float*)d_in[1];
    const float* finW  = (const float*)d_in[2];
    const float* finb  = (const float*)d_in[3];
    const float* freq  = (const float*)d_in[4];
    const float* midW  = (const float*)d_in[5];
    const float* midb  = (const float*)d_in[6];
    const float* foutW = (const float*)d_in[7];
    const float* projW = (const float*)d_in[8];
    const float* projb = (const float*)d_in[9];
    const float* convW = (const float*)d_in[10];
    const float* convb = (const float*)d_in[11];
    const float* fbias = (const float*)d_in[12];
    const float* outW  = (const float*)d_in[13];
    const float* outb  = (const float*)d_in[14];
    float* y = (float*)d_out;

    const size_t SMEM_FFT = (size_t)NFFT * sizeof(float2); // 64 KB (twiddles via L1)
    cudaFuncSetAttribute(k_fft_filter, cudaFuncAttributeMaxDynamicSharedMemorySize, (int)SMEM_FFT);
    cudaFuncSetAttribute(k_fftconv,    cudaFuncAttributeMaxDynamicSharedMemorySize, (int)SMEM_FFT);

    k_twiddle<<<8, 512>>>();
    k_filter<<<128, 256>>>(z, finW, finb, freq, midW, midb, foutW);
    k_fft_filter<<<384, 512, SMEM_FFT>>>();
    k_sgemm_proj<<<dim3(18, 128), 256>>>(u, projW, projb);
    k_shortconv<<<dim3(128, 24, 4), dim3(32, 32)>>>(convW, convb);
    k_fftconv<<<dim3(768, 2), 512, SMEM_FFT>>>(fbias);
    k_sgemm_out<<<dim3(6, 128), 256>>>(outW, outb, y);
}

// round 16
// speedup vs baseline: 1.9129x; 1.9129x over previous
#include <cuda_runtime.h>
#include <cuda_bf16.h>
#include <math.h>
#include <stdint.h>

#define LSEQ 4096
#define DMODEL 768
#define BATCH 4
#define NFFT 8192
#define HALF_NFFT 4096
#define HSTRIDE 4104   // half-spectrum storage stride (4097 used, padded)

// ---------------- scratch (device globals; no allocation allowed) ----------------
__device__ float  g_h[(size_t)LSEQ * DMODEL];                    // filters h[t][d]
__device__ float2 g_Hf[(size_t)DMODEL * HSTRIDE];                // natural-order half spectra
__device__ float  g_up[(size_t)BATCH * LSEQ * 2304];             // u @ proj_W + b
__device__ float  g_qT[(size_t)BATCH * DMODEL * LSEQ];           // q = v*x0, channel-major
__device__ float  g_x1T[(size_t)BATCH * DMODEL * LSEQ];          // x1, channel-major
__device__ float  g_wT[(size_t)BATCH * DMODEL * LSEQ];           // (vnew*x1), channel-major
__device__ float2 g_tw[HALF_NFFT];                               // twiddles exp(-2*pi*i*k/NFFT)

__device__ __forceinline__ int br13(int k) { return (int)(__brev((unsigned)k) >> 19); }

// ---------------- packed f32x2 helpers (Blackwell base ISA) ----------------
__device__ __forceinline__ void ffma2(unsigned long long& d, unsigned long long a,
                                      unsigned long long b) {
    asm("fma.rn.f32x2 %0, %1, %2, %0;" : "+l"(d) : "l"(a), "l"(b));
}
__device__ __forceinline__ unsigned long long pack2(float v) {
    unsigned long long r;
    asm("mov.b64 %0, {%1, %1};" : "=l"(r) : "f"(v));
    return r;
}
__device__ __forceinline__ unsigned long long packab(float lo, float hi) {
    unsigned long long r;
    asm("mov.b64 %0, {%1, %2};" : "=l"(r) : "f"(lo), "f"(hi));
    return r;
}
__device__ __forceinline__ float2 unpack2(unsigned long long v) {
    float2 r;
    asm("mov.b64 {%0, %1}, %2;" : "=f"(r.x), "=f"(r.y) : "l"(v));
    return r;
}

// ---------------- twiddle init ----------------
__global__ void k_twiddle() {
    int k = blockIdx.x * blockDim.x + threadIdx.x;
    if (k < HALF_NFFT) {
        double s, c;
        sincospi(-2.0 * (double)k / (double)NFFT, &s, &c);
        g_tw[k] = make_float2((float)c, (float)s);
    }
}

// ---------------- filter MLP: h[t][d] ----------------
__global__ void k_filter(const float* __restrict__ z, const float* __restrict__ finW,
                         const float* __restrict__ finb, const float* __restrict__ freq,
                         const float* __restrict__ midW, const float* __restrict__ midb,
                         const float* __restrict__ foutW) {
    __shared__ float s_x[32][66];
    __shared__ float s_y[32][66];
    __shared__ float s_w[65][65];
    __shared__ float s_bias[64];
    __shared__ float s_freq[64];
    int t0 = blockIdx.x * 32;
    int tid = threadIdx.x;

    for (int i = tid; i < 32 * 65; i += 256) {
        int r = i / 65, c = i % 65;
        s_x[r][c] = z[(size_t)(t0 + r) * 65 + c];
    }
    for (int i = tid; i < 65 * 64; i += 256) s_w[i / 64][i % 64] = finW[i];
    if (tid < 64) { s_bias[tid] = finb[tid]; s_freq[tid] = freq[tid]; }
    __syncthreads();

    for (int i = tid; i < 2048; i += 256) {
        int r = i >> 6, j = i & 63;
        float acc = s_bias[j];
        #pragma unroll
        for (int kk = 0; kk < 65; kk++) acc += s_x[r][kk] * s_w[kk][j];
        s_y[r][j] = sinf(s_freq[j] * acc);
    }
    __syncthreads();

    for (int layer = 0; layer < 2; layer++) {
        for (int i = tid; i < 4096; i += 256) s_w[i >> 6][i & 63] = midW[layer * 4096 + i];
        if (tid < 64) s_bias[tid] = midb[layer * 64 + tid];
        __syncthreads();
        float (*src)[66] = (layer == 0) ? s_y : s_x;
        float (*dst)[66] = (layer == 0) ? s_x : s_y;
        for (int i = tid; i < 2048; i += 256) {
            int r = i >> 6, j = i & 63;
            float acc = s_bias[j];
            #pragma unroll
            for (int kk = 0; kk < 64; kk++) acc += src[r][kk] * s_w[kk][j];
            dst[r][j] = sinf(s_freq[j] * acc);
        }
        __syncthreads();
    }
    const float LOGT = -4.605170185988091f;            // ln(0.01)
    const float mind = LOGT / 1.5f;
    const float maxd = LOGT / 0.3f;
    for (int c = 0; c < 12; c++) {
        for (int i = tid; i < 4096; i += 256)
            s_w[i >> 6][i & 63] = foutW[(size_t)(i >> 6) * 768 + c * 64 + (i & 63)];
        __syncthreads();
        for (int i = tid; i < 2048; i += 256) {
            int r = i >> 6, dd = i & 63;
            float acc = 0.f;
            #pragma unroll
            for (int j = 0; j < 64; j++) acc += s_y[r][j] * s_w[j][dd];
            int t = t0 + r;
            int d = c * 64 + dd;
            float delta = fabsf(mind + (maxd - mind) * (float)d / 767.0f);
            float tt = (float)t / 4095.0f;
            g_h[(size_t)t * 768 + d] = acc * expf(-tt * delta);
        }
        __syncthreads();
    }
}

// ---------------- FFT primitives (radix-2; twiddles read from L1-cached global) ----------------
__device__ __forceinline__ void fft_dif(float2* x, const float2* __restrict__ tw, int tid) {
    #pragma unroll 1
    for (int s = 0; s < 13; s++) {
        int m = 4096 >> s;
        #pragma unroll
        for (int k = 0; k < 8; k++) {
            int bidx = tid + k * 512;
            int j = bidx & (m - 1);
            int g = bidx >> (12 - s);
            int i1 = (g << (13 - s)) + j;
            int i2 = i1 + m;
            float2 a = x[i1], c = x[i2];
            x[i1] = make_float2(a.x + c.x, a.y + c.y);
            float2 w = __ldg(&tw[j << s]);
            float dr = a.x - c.x, di = a.y - c.y;
            x[i2] = make_float2(dr * w.x - di * w.y, dr * w.y + di * w.x);
        }
        __syncthreads();
    }
}

__device__ __forceinline__ void fft_dit_inv(float2* x, const float2* __restrict__ tw, int tid) {
    #pragma unroll 1
    for (int s = 0; s < 13; s++) {
        int m = 1 << s;
        #pragma unroll
        for (int k = 0; k < 8; k++) {
            int bidx = tid + k * 512;
            int j = bidx & (m - 1);
            int g = bidx >> s;
            int i1 = (g << (s + 1)) + j;
            int i2 = i1 + m;
            float2 a = x[i1], b = x[i2];
            float2 w = __ldg(&tw[j << (12 - s)]);
            float cr = b.x * w.x + b.y * w.y;   // b * conj(w)
            float ci = b.y * w.x - b.x * w.y;
            x[i1] = make_float2(a.x + cr, a.y + ci);
            x[i2] = make_float2(a.x - cr, a.y - ci);
        }
        __syncthreads();
    }
}

// ---------------- filter FFT: one block per PAIR of channels ----------------
__global__ void k_fft_filter() {
    extern __shared__ unsigned char s_raw[];
    float2* x = (float2*)s_raw;
    int d0 = blockIdx.x * 2;
    int d1 = d0 + 1;
    int tid = threadIdx.x; // 512
    for (int i = tid; i < NFFT; i += 512) {
        float re = (i < LSEQ) ? g_h[(size_t)i * 768 + d0] : 0.f;
        float im = (i < LSEQ) ? g_h[(size_t)i * 768 + d1] : 0.f;
        x[i] = make_float2(re, im);
    }
    __syncthreads();
    fft_dif(x, g_tw, tid);
    const float sc = 0.5f / (float)NFFT;
    for (int k = tid; k <= HALF_NFFT; k += 512) {
        float2 Zk = x[br13(k)];
        float2 Zm = x[br13((NFFT - k) & (NFFT - 1))];
        float2 H0 = make_float2(sc * (Zk.x + Zm.x), sc * (Zk.y - Zm.y));
        float2 H1 = make_float2(sc * (Zk.y + Zm.y), sc * (Zm.x - Zk.x));
        g_Hf[(size_t)d0 * HSTRIDE + k] = H0;
        g_Hf[(size_t)d1 * HSTRIDE + k] = H1;
    }
}

// ---------------- GEMM helpers (R11/R14 exact) ----------------
__device__ __forceinline__ void stage_B(unsigned long long (*Bs2)[64],
                                        const float* __restrict__ B, int N,
                                        int k0, int bn, int tid) {
    #pragma unroll
    for (int li = 0; li < 2; li++) {
        int id = tid + li * 256;
        int brow = id >> 5, bc = (id & 31) * 4;
        float4 v = *(const float4*)&B[(size_t)(k0 + brow) * N + bn + bc];
        int txp = bc >> 3;
        int jpA = (bc & 7) >> 1;                 // 0 or 2
        Bs2[brow][jpA * 16 + txp]       = packab(v.x, v.y);
        Bs2[brow][(jpA + 1) * 16 + txp] = packab(v.z, v.w);
    }
}

__device__ __forceinline__ void gemm_step(const float (*As)[128],
                                          const unsigned long long (*Bs2)[64],
                                          int kk, int tx, int ty,
                                          unsigned long long (&acc2)[8][4]) {
    float4 a0 = *(const float4*)&As[kk][ty * 8];
    float4 a1 = *(const float4*)&As[kk][ty * 8 + 4];
    unsigned long long a2[8];
    a2[0] = pack2(a0.x); a2[1] = pack2(a0.y);
    a2[2] = pack2(a0.z); a2[3] = pack2(a0.w);
    a2[4] = pack2(a1.x); a2[5] = pack2(a1.y);
    a2[6] = pack2(a1.z); a2[7] = pack2(a1.w);
    unsigned long long b2[4];
    #pragma unroll
    for (int jp = 0; jp < 4; jp++)
        b2[jp] = Bs2[kk][jp * 16 + tx];
    #pragma unroll
    for (int i = 0; i < 8; i++)
        #pragma unroll
        for (int jp = 0; jp < 4; jp++)
            ffma2(acc2[i][jp], a2[i], b2[jp]);
}

// ---------------- proj GEMM: up = u @ proj_W + proj_b ----------------
__global__ void __launch_bounds__(256, 2) k_sgemm_proj(
    const float* __restrict__ A, const float* __restrict__ B,
    const float* __restrict__ bias) {
    const int K = 768, N = 2304;
    __shared__ float As[16][128];
    __shared__ unsigned long long Bs2[16][64];
    int tid = threadIdx.x;
    int bm = blockIdx.y * 128, bn = blockIdx.x * 128;
    int tx = tid & 15, ty = tid >> 4;
    unsigned long long acc2[8][4];
    #pragma unroll
    for (int i = 0; i < 8; i++)
        #pragma unroll
        for (int j = 0; j < 4; j++) acc2[i][j] = 0ull;

    for (int k0 = 0; k0 < K; k0 += 16) {
        #pragma unroll
        for (int li = 0; li < 2; li++) {
            int id = tid + li * 256;
            int ar = id >> 2, ac = (id & 3) * 4;
            float4 v = *(const float4*)&A[(size_t)(bm + ar) * K + k0 + ac];
            As[ac + 0][ar] = v.x; As[ac + 1][ar] = v.y;
            As[ac + 2][ar] = v.z; As[ac + 3][ar] = v.w;
        }
        stage_B(Bs2, B, N, k0, bn, tid);
        __syncthreads();
        #pragma unroll
        for (int kk = 0; kk < 16; kk++)
            gemm_step(As, Bs2, kk, tx, ty, acc2);
        __syncthreads();
    }
    #pragma unroll
    for (int i = 0; i < 8; i++) {
        size_t row = (size_t)(bm + ty * 8 + i) * N + bn + tx * 8;
        #pragma unroll
        for (int jp = 0; jp < 4; jp++) {
            float2 v = unpack2(acc2[i][jp]);
            g_up[row + jp * 2 + 0] = v.x + bias[bn + tx * 8 + jp * 2 + 0];
            g_up[row + jp * 2 + 1] = v.y + bias[bn + tx * 8 + jp * 2 + 1];
        }
    }
}

// ---------------- short conv + split + transpose ----------------
__global__ void k_shortconv(const float* __restrict__ cw, const float* __restrict__ cb) {
    __shared__ float sq[32][33];
    __shared__ float sx1[32][33];
    int b = blockIdx.z;
    int t0 = blockIdx.x * 32, d0 = blockIdx.y * 32;
    int tx = threadIdx.x, ty = threadIdx.y;
    int t = t0 + ty;
    const float* up = g_up + (size_t)b * LSEQ * 2304;
    float vals[3];
    #pragma unroll
    for (int p = 0; p < 3; p++) {
        int c = d0 + tx + p * 768;
        float w0 = cw[c], w1 = cw[2304 + c], w2 = cw[4608 + c];
        float u2 = up[(size_t)t * 2304 + c];
        float u1 = (t >= 1) ? up[(size_t)(t - 1) * 2304 + c] : 0.f;
        float u0 = (t >= 2) ? up[(size_t)(t - 2) * 2304 + c] : 0.f;
        vals[p] = w0 * u0 + w1 * u1 + w2 * u2 + cb[c];
    }
    sq[ty][tx] = vals[2] * vals[0];   // q = v * x0
    sx1[ty][tx] = vals[1];
    __syncthreads();
    size_t o = ((size_t)b * DMODEL + d0 + ty) * LSEQ + t0 + tx;
    g_qT[o]  = sq[tx][ty];
    g_x1T[o] = sx1[tx][ty];
}

// ---------------- FFT conv: one block per (channel, batch-pair) ----------------
__global__ void k_fftconv(const float* __restrict__ fb) {
    extern __shared__ unsigned char s_raw[];
    float2* x = (float2*)s_raw;
    int d = blockIdx.x, bp = blockIdx.y;
    int b0 = bp * 2, b1 = b0 + 1;
    int tid = threadIdx.x; // 512
    size_t base0 = ((size_t)b0 * DMODEL + d) * LSEQ;
    size_t base1 = ((size_t)b1 * DMODEL + d) * LSEQ;
    const float* q0 = g_qT + base0;
    const float* q1 = g_qT + base1;

    float qr0[8], qr1[8];
    #pragma unroll
    for (int k = 0; k < 8; k++) {
        int i = tid + k * 512;
        qr0[k] = q0[i];
        qr1[k] = q1[i];
        x[i] = make_float2(qr0[k], qr1[k]);
    }
    #pragma unroll
    for (int k = 0; k < 8; k++) x[LSEQ + tid + k * 512] = make_float2(0.f, 0.f);
    __syncthreads();

    fft_dif(x, g_tw, tid);

    const float2* H = g_Hf + (size_t)d * HSTRIDE;
    for (int idx = tid; idx < HALF_NFFT; idx += 512) {
        if (idx == 0) {
            #pragma unroll
            for (int e = 0; e < 2; e++) {
                int pos = e;                       // br(0)=0, br(4096)=1
                float2 Z = x[pos];
                float2 h = H[e == 0 ? 0 : HALF_NFFT];
                float2 Y0 = make_float2(Z.x * h.x, Z.x * h.y);
                float2 Y1 = make_float2(Z.y * h.x, Z.y * h.y);
                x[pos] = make_float2(Y0.x - Y1.y, Y0.y + Y1.x);
            }
        } else {
            int k = idx;
            int p1 = br13(k);
            int p2 = br13(NFFT - k);
            float2 Zk = x[p1], Zm = x[p2];
            float2 Q0 = make_float2(0.5f * (Zk.x + Zm.x), 0.5f * (Zk.y - Zm.y));
            float2 Q1 = make_float2(0.5f * (Zk.y + Zm.y), 0.5f * (Zm.x - Zk.x));
            float2 h = H[k];
            float2 Y0 = make_float2(Q0.x * h.x - Q0.y * h.y, Q0.x * h.y + Q0.y * h.x);
            float2 Y1 = make_float2(Q1.x * h.x - Q1.y * h.y, Q1.x * h.y + Q1.y * h.x);
            x[p1] = make_float2(Y0.x - Y1.y, Y0.y + Y1.x);       // W(k)
            x[p2] = make_float2(Y0.x + Y1.y, Y1.x - Y0.y);       // W(N-k)
        }
    }
    __syncthreads();

    fft_dit_inv(x, g_tw, tid);

    float bias = fb[d];
    const float* x10 = g_x1T + base0;
    const float* x11 = g_x1T + base1;
    float* w0 = g_wT + base0;
    float* w1 = g_wT + base1;
    #pragma unroll
    for (int k = 0; k < 8; k++) {
        int i = tid + k * 512;
        float2 v = x[i];
        w0[i] = (v.x + qr0[k] * bias) * x10[i];
        w1[i] = (v.y + qr1[k] * bias) * x11[i];
    }
}

// ---------------- out GEMM: y = w @ out_W + out_b ----------------
__global__ void __launch_bounds__(256, 2) k_sgemm_out(
    const float* __restrict__ B, const float* __restrict__ bias,
    float* __restrict__ C) {
    const int K = 768, N = 768;
    __shared__ float As[16][128];
    __shared__ unsigned long long Bs2[16][64];
    int tid = threadIdx.x;
    int bm = blockIdx.y * 128, bn = blockIdx.x * 128;
    int b = bm >> 12;
    int t0 = bm & 4095;
    const float* Ab = g_wT + (size_t)b * DMODEL * LSEQ + t0; // A[i,k] = Ab[k*4096 + i]
    int tx = tid & 15, ty = tid >> 4;
    unsigned long long acc2[8][4];
    #pragma unroll
    for (int i = 0; i < 8; i++)
        #pragma unroll
        for (int j = 0; j < 4; j++) acc2[i][j] = 0ull;

    for (int k0 = 0; k0 < K; k0 += 16) {
        #pragma unroll
        for (int li = 0; li < 2; li++) {
            int id = tid + li * 256;
            int kc = id >> 5, i4 = (id & 31) * 4;
            *(float4*)&As[kc][i4] = *(const float4*)&Ab[(size_t)(k0 + kc) * LSEQ + i4];
        }
        stage_B(Bs2, B, N, k0, bn, tid);
        __syncthreads();
        #pragma unroll
        for (int kk = 0; kk < 16; kk++)
            gemm_step(As, Bs2, kk, tx, ty, acc2);
        __syncthreads();
    }
    #pragma unroll
    for (int i = 0; i < 8; i++) {
        size_t row = (size_t)(bm + ty * 8 + i) * N + bn + tx * 8;
        #pragma unroll
        for (int jp = 0; jp < 4; jp++) {
            float2 v = unpack2(acc2[i][jp]);
            C[row + jp * 2 + 0] = v.x + bias[bn + tx * 8 + jp * 2 + 0];
            C[row + jp * 2 + 1] = v.y + bias[bn + tx * 8 + jp * 2 + 1];
        }
    }
}

// ---------------- launch ----------------
extern "C" void kernel_launch(void* const* d_in, const int* in_sizes, int n_in,
                              void* d_out, int out_size) {
    (void)in_sizes; (void)n_in; (void)out_size;
    const float* u     = (const float*)d_in[0];
    const float* z     = (const float*)d_in[1];
    const float* finW  = (const float*)d_in[2];
    const float* finb  = (const float*)d_in[3];
    const float* freq  = (const float*)d_in[4];
    const float* midW  = (const float*)d_in[5];
    const float* midb  = (const float*)d_in[6];
    const float* foutW = (const float*)d_in[7];
    const float* projW = (const float*)d_in[8];
    const float* projb = (const float*)d_in[9];
    const float* convW = (const float*)d_in[10];
    const float* convb = (const float*)d_in[11];
    const float* fbias = (const float*)d_in[12];
    const float* outW  = (const float*)d_in[13];
    const float* outb  = (const float*)d_in[14];
    float* y = (float*)d_out;

    const size_t SMEM_FFT = (size_t)NFFT * sizeof(float2); // 64 KB (twiddles via L1)
    cudaFuncSetAttribute(k_fft_filter, cudaFuncAttributeMaxDynamicSharedMemorySize, (int)SMEM_FFT);
    cudaFuncSetAttribute(k_fftconv,    cudaFuncAttributeMaxDynamicSharedMemorySize, (int)SMEM_FFT);

    k_twiddle<<<8, 512>>>();
    k_filter<<<128, 256>>>(z, finW, finb, freq, midW, midb, foutW);
    k_fft_filter<<<384, 512, SMEM_FFT>>>();
    k_sgemm_proj<<<dim3(18, 128), 256>>>(u, projW, projb);
    k_shortconv<<<dim3(128, 24, 4), dim3(32, 32)>>>(convW, convb);
    k_fftconv<<<dim3(768, 2), 512, SMEM_FFT>>>(fbias);
    k_sgemm_out<<<dim3(6, 128), 256>>>(outW, outb, y);
}

// round 17
// speedup vs baseline: 1.9963x; 1.0436x over previous
#include <cuda_runtime.h>
#include <cuda_bf16.h>
#include <math.h>
#include <stdint.h>

#define LSEQ 4096
#define DMODEL 768
#define BATCH 4
#define NFFT 8192
#define HALF_NFFT 4096
#define HSTRIDE 4104   // half-spectrum storage stride (4097 used, padded)

// ---------------- scratch (device globals; no allocation allowed) ----------------
__device__ float  g_h[(size_t)LSEQ * DMODEL];                    // filters h[t][d]
__device__ float2 g_Hf[(size_t)DMODEL * HSTRIDE];                // natural-order half spectra
__device__ float  g_up[(size_t)BATCH * LSEQ * 2304];             // u @ proj_W + b
__device__ float  g_qT[(size_t)BATCH * DMODEL * LSEQ];           // q = v*x0, channel-major
__device__ float  g_x1T[(size_t)BATCH * DMODEL * LSEQ];          // x1, channel-major
__device__ float  g_wT[(size_t)BATCH * DMODEL * LSEQ];           // (vnew*x1), channel-major
__device__ float2 g_tw[HALF_NFFT];                               // twiddles exp(-2*pi*i*k/NFFT)

__device__ __forceinline__ int br13(int k) { return (int)(__brev((unsigned)k) >> 19); }

// ---------------- packed f32x2 helpers (Blackwell base ISA) ----------------
__device__ __forceinline__ void ffma2(unsigned long long& d, unsigned long long a,
                                      unsigned long long b) {
    asm("fma.rn.f32x2 %0, %1, %2, %0;" : "+l"(d) : "l"(a), "l"(b));
}
__device__ __forceinline__ unsigned long long pack2(float v) {
    unsigned long long r;
    asm("mov.b64 %0, {%1, %1};" : "=l"(r) : "f"(v));
    return r;
}
__device__ __forceinline__ unsigned long long packab(float lo, float hi) {
    unsigned long long r;
    asm("mov.b64 %0, {%1, %2};" : "=l"(r) : "f"(lo), "f"(hi));
    return r;
}
__device__ __forceinline__ float2 unpack2(unsigned long long v) {
    float2 r;
    asm("mov.b64 {%0, %1}, %2;" : "=f"(r.x), "=f"(r.y) : "l"(v));
    return r;
}

// ---------------- twiddle init ----------------
__global__ void k_twiddle() {
    int k = blockIdx.x * blockDim.x + threadIdx.x;
    if (k < HALF_NFFT) {
        double s, c;
        sincospi(-2.0 * (double)k / (double)NFFT, &s, &c);
        g_tw[k] = make_float2((float)c, (float)s);
    }
}

// ---------------- filter MLP: h[t][d] ----------------
__global__ void k_filter(const float* __restrict__ z, const float* __restrict__ finW,
                         const float* __restrict__ finb, const float* __restrict__ freq,
                         const float* __restrict__ midW, const float* __restrict__ midb,
                         const float* __restrict__ foutW) {
    __shared__ float s_x[32][66];
    __shared__ float s_y[32][66];
    __shared__ float s_w[65][65];
    __shared__ float s_bias[64];
    __shared__ float s_freq[64];
    int t0 = blockIdx.x * 32;
    int tid = threadIdx.x;

    for (int i = tid; i < 32 * 65; i += 256) {
        int r = i / 65, c = i % 65;
        s_x[r][c] = z[(size_t)(t0 + r) * 65 + c];
    }
    for (int i = tid; i < 65 * 64; i += 256) s_w[i / 64][i % 64] = finW[i];
    if (tid < 64) { s_bias[tid] = finb[tid]; s_freq[tid] = freq[tid]; }
    __syncthreads();

    for (int i = tid; i < 2048; i += 256) {
        int r = i >> 6, j = i & 63;
        float acc = s_bias[j];
        #pragma unroll
        for (int kk = 0; kk < 65; kk++) acc += s_x[r][kk] * s_w[kk][j];
        s_y[r][j] = sinf(s_freq[j] * acc);
    }
    __syncthreads();

    for (int layer = 0; layer < 2; layer++) {
        for (int i = tid; i < 4096; i += 256) s_w[i >> 6][i & 63] = midW[layer * 4096 + i];
        if (tid < 64) s_bias[tid] = midb[layer * 64 + tid];
        __syncthreads();
        float (*src)[66] = (layer == 0) ? s_y : s_x;
        float (*dst)[66] = (layer == 0) ? s_x : s_y;
        for (int i = tid; i < 2048; i += 256) {
            int r = i >> 6, j = i & 63;
            float acc = s_bias[j];
            #pragma unroll
            for (int kk = 0; kk < 64; kk++) acc += src[r][kk] * s_w[kk][j];
            dst[r][j] = sinf(s_freq[j] * acc);
        }
        __syncthreads();
    }
    const float LOGT = -4.605170185988091f;            // ln(0.01)
    const float mind = LOGT / 1.5f;
    const float maxd = LOGT / 0.3f;
    for (int c = 0; c < 12; c++) {
        for (int i = tid; i < 4096; i += 256)
            s_w[i >> 6][i & 63] = foutW[(size_t)(i >> 6) * 768 + c * 64 + (i & 63)];
        __syncthreads();
        for (int i = tid; i < 2048; i += 256) {
            int r = i >> 6, dd = i & 63;
            float acc = 0.f;
            #pragma unroll
            for (int j = 0; j < 64; j++) acc += s_y[r][j] * s_w[j][dd];
            int t = t0 + r;
            int d = c * 64 + dd;
            float delta = fabsf(mind + (maxd - mind) * (float)d / 767.0f);
            float tt = (float)t / 4095.0f;
            g_h[(size_t)t * 768 + d] = acc * expf(-tt * delta);
        }
        __syncthreads();
    }
}

// ---------------- FFT primitives (radix-2; twiddles read from L1-cached global) ----------------
__device__ __forceinline__ void fft_dif(float2* x, const float2* __restrict__ tw, int tid) {
    #pragma unroll 1
    for (int s = 0; s < 13; s++) {
        int m = 4096 >> s;
        #pragma unroll
        for (int k = 0; k < 8; k++) {
            int bidx = tid + k * 512;
            int j = bidx & (m - 1);
            int g = bidx >> (12 - s);
            int i1 = (g << (13 - s)) + j;
            int i2 = i1 + m;
            float2 a = x[i1], c = x[i2];
            x[i1] = make_float2(a.x + c.x, a.y + c.y);
            float2 w = __ldg(&tw[j << s]);
            float dr = a.x - c.x, di = a.y - c.y;
            x[i2] = make_float2(dr * w.x - di * w.y, dr * w.y + di * w.x);
        }
        __syncthreads();
    }
}

__device__ __forceinline__ void fft_dit_inv(float2* x, const float2* __restrict__ tw, int tid) {
    #pragma unroll 1
    for (int s = 0; s < 13; s++) {
        int m = 1 << s;
        #pragma unroll
        for (int k = 0; k < 8; k++) {
            int bidx = tid + k * 512;
            int j = bidx & (m - 1);
            int g = bidx >> s;
            int i1 = (g << (s + 1)) + j;
            int i2 = i1 + m;
            float2 a = x[i1], b = x[i2];
            float2 w = __ldg(&tw[j << (12 - s)]);
            float cr = b.x * w.x + b.y * w.y;   // b * conj(w)
            float ci = b.y * w.x - b.x * w.y;
            x[i1] = make_float2(a.x + cr, a.y + ci);
            x[i2] = make_float2(a.x - cr, a.y - ci);
        }
        __syncthreads();
    }
}

// ---------------- filter FFT: one block per PAIR of channels ----------------
__global__ void k_fft_filter() {
    extern __shared__ unsigned char s_raw[];
    float2* x = (float2*)s_raw;
    int d0 = blockIdx.x * 2;
    int d1 = d0 + 1;
    int tid = threadIdx.x; // 512
    for (int i = tid; i < NFFT; i += 512) {
        float re = (i < LSEQ) ? g_h[(size_t)i * 768 + d0] : 0.f;
        float im = (i < LSEQ) ? g_h[(size_t)i * 768 + d1] : 0.f;
        x[i] = make_float2(re, im);
    }
    __syncthreads();
    fft_dif(x, g_tw, tid);
    const float sc = 0.5f / (float)NFFT;
    for (int k = tid; k <= HALF_NFFT; k += 512) {
        float2 Zk = x[br13(k)];
        float2 Zm = x[br13((NFFT - k) & (NFFT - 1))];
        float2 H0 = make_float2(sc * (Zk.x + Zm.x), sc * (Zk.y - Zm.y));
        float2 H1 = make_float2(sc * (Zk.y + Zm.y), sc * (Zm.x - Zk.x));
        g_Hf[(size_t)d0 * HSTRIDE + k] = H0;
        g_Hf[(size_t)d1 * HSTRIDE + k] = H1;
    }
}

// ---------------- GEMM helpers (R11/R14 exact) ----------------
__device__ __forceinline__ void stage_B(unsigned long long (*Bs2)[64],
                                        const float* __restrict__ B, int N,
                                        int k0, int bn, int tid) {
    #pragma unroll
    for (int li = 0; li < 2; li++) {
        int id = tid + li * 256;
        int brow = id >> 5, bc = (id & 31) * 4;
        float4 v = *(const float4*)&B[(size_t)(k0 + brow) * N + bn + bc];
        int txp = bc >> 3;
        int jpA = (bc & 7) >> 1;                 // 0 or 2
        Bs2[brow][jpA * 16 + txp]       = packab(v.x, v.y);
        Bs2[brow][(jpA + 1) * 16 + txp] = packab(v.z, v.w);
    }
}

__device__ __forceinline__ void gemm_step(const float (*As)[128],
                                          const unsigned long long (*Bs2)[64],
                                          int kk, int tx, int ty,
                                          unsigned long long (&acc2)[8][4]) {
    float4 a0 = *(const float4*)&As[kk][ty * 8];
    float4 a1 = *(const float4*)&As[kk][ty * 8 + 4];
    unsigned long long a2[8];
    a2[0] = pack2(a0.x); a2[1] = pack2(a0.y);
    a2[2] = pack2(a0.z); a2[3] = pack2(a0.w);
    a2[4] = pack2(a1.x); a2[5] = pack2(a1.y);
    a2[6] = pack2(a1.z); a2[7] = pack2(a1.w);
    unsigned long long b2[4];
    #pragma unroll
    for (int jp = 0; jp < 4; jp++)
        b2[jp] = Bs2[kk][jp * 16 + tx];
    #pragma unroll
    for (int i = 0; i < 8; i++)
        #pragma unroll
        for (int jp = 0; jp < 4; jp++)
            ffma2(acc2[i][jp], a2[i], b2[jp]);
}

// ---------------- proj GEMM: up = u @ proj_W + proj_b ----------------
__global__ void __launch_bounds__(256, 2) k_sgemm_proj(
    const float* __restrict__ A, const float* __restrict__ B,
    const float* __restrict__ bias) {
    const int K = 768, N = 2304;
    __shared__ float As[16][128];
    __shared__ unsigned long long Bs2[16][64];
    int tid = threadIdx.x;
    int bm = blockIdx.y * 128, bn = blockIdx.x * 128;
    int tx = tid & 15, ty = tid >> 4;
    unsigned long long acc2[8][4];
    #pragma unroll
    for (int i = 0; i < 8; i++)
        #pragma unroll
        for (int j = 0; j < 4; j++) acc2[i][j] = 0ull;

    for (int k0 = 0; k0 < K; k0 += 16) {
        #pragma unroll
        for (int li = 0; li < 2; li++) {
            int id = tid + li * 256;
            int ar = id >> 2, ac = (id & 3) * 4;
            float4 v = *(const float4*)&A[(size_t)(bm + ar) * K + k0 + ac];
            As[ac + 0][ar] = v.x; As[ac + 1][ar] = v.y;
            As[ac + 2][ar] = v.z; As[ac + 3][ar] = v.w;
        }
        stage_B(Bs2, B, N, k0, bn, tid);
        __syncthreads();
        #pragma unroll
        for (int kk = 0; kk < 16; kk++)
            gemm_step(As, Bs2, kk, tx, ty, acc2);
        __syncthreads();
    }
    #pragma unroll
    for (int i = 0; i < 8; i++) {
        size_t row = (size_t)(bm + ty * 8 + i) * N + bn + tx * 8;
        #pragma unroll
        for (int jp = 0; jp < 4; jp++) {
            float2 v = unpack2(acc2[i][jp]);
            g_up[row + jp * 2 + 0] = v.x + bias[bn + tx * 8 + jp * 2 + 0];
            g_up[row + jp * 2 + 1] = v.y + bias[bn + tx * 8 + jp * 2 + 1];
        }
    }
}

// ---------------- short conv + split + transpose ----------------
__global__ void k_shortconv(const float* __restrict__ cw, const float* __restrict__ cb) {
    __shared__ float sq[32][33];
    __shared__ float sx1[32][33];
    int b = blockIdx.z;
    int t0 = blockIdx.x * 32, d0 = blockIdx.y * 32;
    int tx = threadIdx.x, ty = threadIdx.y;
    int t = t0 + ty;
    const float* up = g_up + (size_t)b * LSEQ * 2304;
    float vals[3];
    #pragma unroll
    for (int p = 0; p < 3; p++) {
        int c = d0 + tx + p * 768;
        float w0 = cw[c], w1 = cw[2304 + c], w2 = cw[4608 + c];
        float u2 = up[(size_t)t * 2304 + c];
        float u1 = (t >= 1) ? up[(size_t)(t - 1) * 2304 + c] : 0.f;
        float u0 = (t >= 2) ? up[(size_t)(t - 2) * 2304 + c] : 0.f;
        vals[p] = w0 * u0 + w1 * u1 + w2 * u2 + cb[c];
    }
    sq[ty][tx] = vals[2] * vals[0];   // q = v * x0
    sx1[ty][tx] = vals[1];
    __syncthreads();
    size_t o = ((size_t)b * DMODEL + d0 + ty) * LSEQ + t0 + tx;
    g_qT[o]  = sq[tx][ty];
    g_x1T[o] = sx1[tx][ty];
}

// ---------------- FFT conv: one block per (channel, batch-pair) ----------------
__global__ void k_fftconv(const float* __restrict__ fb) {
    extern __shared__ unsigned char s_raw[];
    float2* x = (float2*)s_raw;
    int d = blockIdx.x, bp = blockIdx.y;
    int b0 = bp * 2, b1 = b0 + 1;
    int tid = threadIdx.x; // 512
    size_t base0 = ((size_t)b0 * DMODEL + d) * LSEQ;
    size_t base1 = ((size_t)b1 * DMODEL + d) * LSEQ;
    const float* q0 = g_qT + base0;
    const float* q1 = g_qT + base1;

    float qr0[8], qr1[8];
    #pragma unroll
    for (int k = 0; k < 8; k++) {
        int i = tid + k * 512;
        qr0[k] = q0[i];
        qr1[k] = q1[i];
        x[i] = make_float2(qr0[k], qr1[k]);
    }
    #pragma unroll
    for (int k = 0; k < 8; k++) x[LSEQ + tid + k * 512] = make_float2(0.f, 0.f);
    __syncthreads();

    fft_dif(x, g_tw, tid);

    const float2* H = g_Hf + (size_t)d * HSTRIDE;
    for (int idx = tid; idx < HALF_NFFT; idx += 512) {
        if (idx == 0) {
            #pragma unroll
            for (int e = 0; e < 2; e++) {
                int pos = e;                       // br(0)=0, br(4096)=1
                float2 Z = x[pos];
                float2 h = H[e == 0 ? 0 : HALF_NFFT];
                float2 Y0 = make_float2(Z.x * h.x, Z.x * h.y);
                float2 Y1 = make_float2(Z.y * h.x, Z.y * h.y);
                x[pos] = make_float2(Y0.x - Y1.y, Y0.y + Y1.x);
            }
        } else {
            int k = idx;
            int p1 = br13(k);
            int p2 = br13(NFFT - k);
            float2 Zk = x[p1], Zm = x[p2];
            float2 Q0 = make_float2(0.5f * (Zk.x + Zm.x), 0.5f * (Zk.y - Zm.y));
            float2 Q1 = make_float2(0.5f * (Zk.y + Zm.y), 0.5f * (Zm.x - Zk.x));
            float2 h = H[k];
            float2 Y0 = make_float2(Q0.x * h.x - Q0.y * h.y, Q0.x * h.y + Q0.y * h.x);
            float2 Y1 = make_float2(Q1.x * h.x - Q1.y * h.y, Q1.x * h.y + Q1.y * h.x);
            x[p1] = make_float2(Y0.x - Y1.y, Y0.y + Y1.x);       // W(k)
            x[p2] = make_float2(Y0.x + Y1.y, Y1.x - Y0.y);       // W(N-k)
        }
    }
    __syncthreads();

    fft_dit_inv(x, g_tw, tid);

    float bias = fb[d];
    const float* x10 = g_x1T + base0;
    const float* x11 = g_x1T + base1;
    float* w0 = g_wT + base0;
    float* w1 = g_wT + base1;
    #pragma unroll
    for (int k = 0; k < 8; k++) {
        int i = tid + k * 512;
        float2 v = x[i];
        w0[i] = (v.x + qr0[k] * bias) * x10[i];
        w1[i] = (v.y + qr1[k] * bias) * x11[i];
    }
}

// ---------------- out GEMM: y = w @ out_W + out_b ----------------
__global__ void __launch_bounds__(256, 2) k_sgemm_out(
    const float* __restrict__ B, const float* __restrict__ bias,
    float* __restrict__ C) {
    const int K = 768, N = 768;
    __shared__ float As[16][128];
    __shared__ unsigned long long Bs2[16][64];
    int tid = threadIdx.x;
    int bm = blockIdx.y * 128, bn = blockIdx.x * 128;
    int b = bm >> 12;
    int t0 = bm & 4095;
    const float* Ab = g_wT + (size_t)b * DMODEL * LSEQ + t0; // A[i,k] = Ab[k*4096 + i]
    int tx = tid & 15, ty = tid >> 4;
    unsigned long long acc2[8][4];
    #pragma unroll
    for (int i = 0; i < 8; i++)
        #pragma unroll
        for (int j = 0; j < 4; j++) acc2[i][j] = 0ull;

    for (int k0 = 0; k0 < K; k0 += 16) {
        #pragma unroll
        for (int li = 0; li < 2; li++) {
            int id = tid + li * 256;
            int kc = id >> 5, i4 = (id & 31) * 4;
            *(float4*)&As[kc][i4] = *(const float4*)&Ab[(size_t)(k0 + kc) * LSEQ + i4];
        }
        stage_B(Bs2, B, N, k0, bn, tid);
        __syncthreads();
        #pragma unroll
        for (int kk = 0; kk < 16; kk++)
            gemm_step(As, Bs2, kk, tx, ty, acc2);
        __syncthreads();
    }
    #pragma unroll
    for (int i = 0; i < 8; i++) {
        size_t row = (size_t)(bm + ty * 8 + i) * N + bn + tx * 8;
        #pragma unroll
        for (int jp = 0; jp < 4; jp++) {
            float2 v = unpack2(acc2[i][jp]);
            C[row + jp * 2 + 0] = v.x + bias[bn + tx * 8 + jp * 2 + 0];
            C[row + jp * 2 + 1] = v.y + bias[bn + tx * 8 + jp * 2 + 1];
        }
    }
}

// ---------------- launch (forked side stream: filter chain overlaps proj GEMM) ----------------
extern "C" void kernel_launch(void* const* d_in, const int* in_sizes, int n_in,
                              void* d_out, int out_size) {
    (void)in_sizes; (void)n_in; (void)out_size;
    const float* u     = (const float*)d_in[0];
    const float* z     = (const float*)d_in[1];
    const float* finW  = (const float*)d_in[2];
    const float* finb  = (const float*)d_in[3];
    const float* freq  = (const float*)d_in[4];
    const float* midW  = (const float*)d_in[5];
    const float* midb  = (const float*)d_in[6];
    const float* foutW = (const float*)d_in[7];
    const float* projW = (const float*)d_in[8];
    const float* projb = (const float*)d_in[9];
    const float* convW = (const float*)d_in[10];
    const float* convb = (const float*)d_in[11];
    const float* fbias = (const float*)d_in[12];
    const float* outW  = (const float*)d_in[13];
    const float* outb  = (const float*)d_in[14];
    float* y = (float*)d_out;

    const size_t SMEM_FFT = (size_t)NFFT * sizeof(float2); // 64 KB (twiddles via L1)
    cudaFuncSetAttribute(k_fft_filter, cudaFuncAttributeMaxDynamicSharedMemorySize, (int)SMEM_FFT);
    cudaFuncSetAttribute(k_fftconv,    cudaFuncAttributeMaxDynamicSharedMemorySize, (int)SMEM_FFT);

    // Fork a non-blocking side stream for the filter chain (independent of proj).
    // Created per call and intentionally not destroyed: destroying resources that
    // participated in an ongoing stream capture is illegal, and kernel_launch is
    // only invoked a handful of times (correctness + capture).
    cudaStream_t side;
    cudaEvent_t eFork, eJoin;
    cudaStreamCreateWithFlags(&side, cudaStreamNonBlocking);
    cudaEventCreateWithFlags(&eFork, cudaEventDisableTiming);
    cudaEventCreateWithFlags(&eJoin, cudaEventDisableTiming);

    cudaEventRecord(eFork, 0);
    cudaStreamWaitEvent(side, eFork, 0);

    // side chain: twiddles -> filter MLP -> filter spectra
    k_twiddle<<<8, 512, 0, side>>>();
    k_filter<<<128, 256, 0, side>>>(z, finW, finb, freq, midW, midb, foutW);
    k_fft_filter<<<384, 512, SMEM_FFT, side>>>();
    cudaEventRecord(eJoin, side);

    // main chain (default stream): proj GEMM -> short conv
    k_sgemm_proj<<<dim3(18, 128), 256>>>(u, projW, projb);
    k_shortconv<<<dim3(128, 24, 4), dim3(32, 32)>>>(convW, convb);

    // join: fftconv needs g_tw + g_Hf from the side chain
    cudaStreamWaitEvent(0, eJoin, 0);
    k_fftconv<<<dim3(768, 2), 512, SMEM_FFT>>>(fbias);
    k_sgemm_out<<<dim3(6, 128), 256>>>(outW, outb, y);
}